// round 9
// baseline (speedup 1.0000x reference)
#include <cuda_runtime.h>

#define BSZ 4096
#define TSZ 4096
#define NTOT ((long)BSZ * TSZ)

// per-chain loss partials
__device__ double g_loss_partial[BSZ];

__device__ __forceinline__ float tanhx(float x) {
    float y; asm("tanh.approx.f32 %0, %1;" : "=f"(y) : "f"(x)); return y;
}

// One thread per batch element; writes x_pad + output directly, accumulates loss.
__global__ void __launch_bounds__(32, 1) gru_kernel(
    const float* __restrict__ x, const int* __restrict__ lens,
    const float* __restrict__ eWih, const float* __restrict__ eWhh,
    const float* __restrict__ ebih, const float* __restrict__ ebhh,
    const float* __restrict__ dWih, const float* __restrict__ dWhh,
    const float* __restrict__ dbih, const float* __restrict__ dbhh,
    const float* __restrict__ linW, const float* __restrict__ linb,
    float* __restrict__ out_xpad, float* __restrict__ out_output)
{
    const int b   = blockIdx.x * 32 + threadIdx.x;
    const int len = lens[b];
    const float* __restrict__ xrow    = x + (long)b * TSZ;
    float* __restrict__ xpadrow = out_xpad   + (long)b * TSZ;
    float* __restrict__ orow    = out_output + (long)b * TSZ;

    float h0 = 0.f, h1 = 0.f, h2 = 0.f;
    float c0 = 0.f, c1 = 0.f, c2 = 0.f;      // captured h at t == len-1

    // ================= encoder =================
    {
        float wi[6], bs[6], w0[6], w1[6], w2[6];
#pragma unroll
        for (int g = 0; g < 6; g++) {
            wi[g] = 0.5f * eWih[g];
            bs[g] = 0.5f * (ebih[g] + ebhh[g]);
            w0[g] = 0.5f * eWhh[g * 3 + 0];
            w1[g] = 0.5f * eWhh[g * 3 + 1];
            w2[g] = 0.5f * eWhh[g * 3 + 2];
        }
        float win[3], bin_[3], bhn[3], wn0[3], wn1[3], wn2[3];
#pragma unroll
        for (int k = 0; k < 3; k++) {
            win[k]  = eWih[6 + k];
            bin_[k] = ebih[6 + k];
            bhn[k]  = ebhh[6 + k];
            wn0[k]  = eWhh[(6 + k) * 3 + 0];
            wn1[k]  = eWhh[(6 + k) * 3 + 1];
            wn2[k]  = eWhh[(6 + k) * 3 + 2];
        }
        const int len_m1 = len - 1;

        auto enc_step = [&](float xv, int t) {
            float gi[6];
#pragma unroll
            for (int g = 0; g < 6; g++) gi[g] = fmaf(xv, wi[g], bs[g]);
            float i0 = fmaf(xv, win[0], bin_[0]);
            float i1 = fmaf(xv, win[1], bin_[1]);
            float i2 = fmaf(xv, win[2], bin_[2]);

            float a[6];
#pragma unroll
            for (int g = 0; g < 6; g++)
                a[g] = fmaf(h2, w2[g], fmaf(h1, w1[g], fmaf(h0, w0[g], gi[g])));
            float hn0 = fmaf(h2, wn2[0], fmaf(h1, wn1[0], fmaf(h0, wn0[0], bhn[0])));
            float hn1 = fmaf(h2, wn2[1], fmaf(h1, wn1[1], fmaf(h0, wn0[1], bhn[1])));
            float hn2 = fmaf(h2, wn2[2], fmaf(h1, wn1[2], fmaf(h0, wn0[2], bhn[2])));

            float tr0 = tanhx(a[0]), tr1 = tanhx(a[1]), tr2 = tanhx(a[2]);
            float tz0 = tanhx(a[3]), tz1 = tanhx(a[4]), tz2 = tanhx(a[5]);

            float r0 = fmaf(tr0, 0.5f, 0.5f), r1 = fmaf(tr1, 0.5f, 0.5f), r2 = fmaf(tr2, 0.5f, 0.5f);
            float m0 = fmaf(tz0, -0.5f, 0.5f), m1 = fmaf(tz1, -0.5f, 0.5f), m2 = fmaf(tz2, -0.5f, 0.5f);

            float n0 = tanhx(fmaf(r0, hn0, i0));
            float n1 = tanhx(fmaf(r1, hn1, i1));
            float n2 = tanhx(fmaf(r2, hn2, i2));

            // h' = h + (1-z)(n-h)
            float nh0 = fmaf(m0, n0 - h0, h0);
            float nh1 = fmaf(m1, n1 - h1, h1);
            float nh2 = fmaf(m2, n2 - h2, h2);
            bool act = t < len;
            h0 = act ? nh0 : h0;
            h1 = act ? nh1 : h1;
            h2 = act ? nh2 : h2;
            if (t == len_m1) { c0 = h0; c1 = h1; c2 = h2; }

            // x_pad store (bubble filler)
            xpadrow[t] = act ? xv : 0.f;
        };

        const int wmax  = __reduce_max_sync(0xFFFFFFFFu, len);
        const int wmax4 = (wmax + 3) & ~3;
        for (int t = 0; t < wmax4; t += 4) {
            const float4 xq = *(const float4*)(xrow + t);
            enc_step(xq.x, t + 0);
            enc_step(xq.y, t + 1);
            enc_step(xq.z, t + 2);
            enc_step(xq.w, t + 3);
        }
        // zero the x_pad tail beyond this warp's max length
        for (int t = wmax4; t < TSZ; t += 4) {
            xpadrow[t + 0] = 0.f;
            xpadrow[t + 1] = 0.f;
            xpadrow[t + 2] = 0.f;
            xpadrow[t + 3] = 0.f;
        }
    }

    // features = sigmoid(captured h)
    h0 = fmaf(tanhx(0.5f * c0), 0.5f, 0.5f);
    h1 = fmaf(tanhx(0.5f * c1), 0.5f, 0.5f);
    h2 = fmaf(tanhx(0.5f * c2), 0.5f, 0.5f);

    // ================= decoder (lin folded into gate weights) =================
    {
        const float lw0 = linW[0], lw1 = linW[1], lw2 = linW[2], lb = linb[0];

        // rz gates: w'[g][k] = 0.5*(Whh[g][k] + Wih[g]*lw[k]); b' = 0.5*(bih+bhh+Wih[g]*lb)
        float w0f[6], w1f[6], w2f[6], bsf[6];
#pragma unroll
        for (int g = 0; g < 6; g++) {
            float wi = dWih[g];
            w0f[g] = 0.5f * fmaf(wi, lw0, dWhh[g * 3 + 0]);
            w1f[g] = 0.5f * fmaf(wi, lw1, dWhh[g * 3 + 1]);
            w2f[g] = 0.5f * fmaf(wi, lw2, dWhh[g * 3 + 2]);
            bsf[g] = 0.5f * (dbih[g] + dbhh[g] + wi * lb);
        }
        // n gates: i'[k] = (Wih_n[k]*lw)·h + (Wih_n[k]*lb + bih_n[k]);  hn unchanged
        float iw0[3], iw1[3], iw2[3], ibf[3], bhn[3], wn0[3], wn1[3], wn2[3];
#pragma unroll
        for (int k = 0; k < 3; k++) {
            float win = dWih[6 + k];
            iw0[k] = win * lw0;
            iw1[k] = win * lw1;
            iw2[k] = win * lw2;
            ibf[k] = fmaf(win, lb, dbih[6 + k]);
            bhn[k] = dbhh[6 + k];
            wn0[k] = dWhh[(6 + k) * 3 + 0];
            wn1[k] = dWhh[(6 + k) * 3 + 1];
            wn2[k] = dWhh[(6 + k) * 3 + 2];
        }

        float acc0 = 0.f, acc1 = 0.f;

        // folded step: everything is a function of h only; outv/store/loss are epilogue
        auto dec_folded = [&](float xv, int t) {
            float a[6];
#pragma unroll
            for (int g = 0; g < 6; g++)
                a[g] = fmaf(h2, w2f[g], fmaf(h1, w1f[g], fmaf(h0, w0f[g], bsf[g])));
            float hn0 = fmaf(h2, wn2[0], fmaf(h1, wn1[0], fmaf(h0, wn0[0], bhn[0])));
            float hn1 = fmaf(h2, wn2[1], fmaf(h1, wn1[1], fmaf(h0, wn0[1], bhn[1])));
            float hn2 = fmaf(h2, wn2[2], fmaf(h1, wn1[2], fmaf(h0, wn0[2], bhn[2])));
            float i0 = fmaf(h2, iw2[0], fmaf(h1, iw1[0], fmaf(h0, iw0[0], ibf[0])));
            float i1 = fmaf(h2, iw2[1], fmaf(h1, iw1[1], fmaf(h0, iw0[1], ibf[1])));
            float i2 = fmaf(h2, iw2[2], fmaf(h1, iw1[2], fmaf(h0, iw0[2], ibf[2])));

            float tr0 = tanhx(a[0]), tr1 = tanhx(a[1]), tr2 = tanhx(a[2]);
            float tz0 = tanhx(a[3]), tz1 = tanhx(a[4]), tz2 = tanhx(a[5]);

            float r0 = fmaf(tr0, 0.5f, 0.5f), r1 = fmaf(tr1, 0.5f, 0.5f), r2 = fmaf(tr2, 0.5f, 0.5f);
            float m0 = fmaf(tz0, -0.5f, 0.5f), m1 = fmaf(tz1, -0.5f, 0.5f), m2 = fmaf(tz2, -0.5f, 0.5f);

            float n0 = tanhx(fmaf(r0, hn0, i0));
            float n1 = tanhx(fmaf(r1, hn1, i1));
            float n2 = tanhx(fmaf(r2, hn2, i2));

            h0 = fmaf(m0, n0 - h0, h0);
            h1 = fmaf(m1, n1 - h1, h1);
            h2 = fmaf(m2, n2 - h2, h2);

            // epilogue (off-chain): output linear, masked store, loss
            float outv = fmaf(h2, lw2, fmaf(h1, lw1, fmaf(h0, lw0, lb)));
            bool valid = t < len;
            float om = valid ? outv : 0.f;
            orow[t] = om;
            float xm = valid ? xv : 0.f;
            float d  = xm - om;
            if (t & 1) acc1 = fmaf(d, d, acc1); else acc0 = fmaf(d, d, acc0);
        };

        // ---- step 0: inp = 0 (unfolded), loads weights straight from global ----
        {
            float a[6];
#pragma unroll
            for (int g = 0; g < 6; g++)
                a[g] = 0.5f * (dbih[g] + dbhh[g]
                       + fmaf(h2, dWhh[g * 3 + 2], fmaf(h1, dWhh[g * 3 + 1], h0 * dWhh[g * 3 + 0])));
            float hn_[3], n_[3];
#pragma unroll
            for (int k = 0; k < 3; k++)
                hn_[k] = dbhh[6 + k]
                       + fmaf(h2, dWhh[(6 + k) * 3 + 2], fmaf(h1, dWhh[(6 + k) * 3 + 1], h0 * dWhh[(6 + k) * 3 + 0]));
#pragma unroll
            for (int k = 0; k < 3; k++) {
                float r = fmaf(tanhx(a[k]), 0.5f, 0.5f);
                n_[k] = tanhx(fmaf(r, hn_[k], dbih[6 + k]));
            }
            float m0 = fmaf(tanhx(a[3]), -0.5f, 0.5f);
            float m1 = fmaf(tanhx(a[4]), -0.5f, 0.5f);
            float m2 = fmaf(tanhx(a[5]), -0.5f, 0.5f);
            h0 = fmaf(m0, n_[0] - h0, h0);
            h1 = fmaf(m1, n_[1] - h1, h1);
            h2 = fmaf(m2, n_[2] - h2, h2);

            float outv = fmaf(h2, lw2, fmaf(h1, lw1, fmaf(h0, lw0, lb)));
            bool valid = 0 < len;
            float om = valid ? outv : 0.f;
            orow[0] = om;
            float xm = valid ? xrow[0] : 0.f;
            float d  = xm - om;
            acc0 = fmaf(d, d, acc0);
        }
        // ---- steps 1..3 (folded, scalar x loads) ----
        dec_folded(xrow[1], 1);
        dec_folded(xrow[2], 2);
        dec_folded(xrow[3], 3);
        // ---- steps 4..4095 (folded, vectorized x loads) ----
        for (int t = 4; t < TSZ; t += 4) {
            const float4 xq = *(const float4*)(xrow + t);
            dec_folded(xq.x, t + 0);
            dec_folded(xq.y, t + 1);
            dec_folded(xq.z, t + 2);
            dec_folded(xq.w, t + 3);
        }

        g_loss_partial[b] = (double)acc0 + (double)acc1;
    }
}

// Deterministic fixed-order reduction of the 4096 partials -> scalar loss
__global__ void loss_kernel(float* __restrict__ out_loss)
{
    __shared__ double s[1024];
    int tid = threadIdx.x;
    double a = 0.0;
    for (int i = tid; i < BSZ; i += 1024) a += g_loss_partial[i];
    s[tid] = a;
    __syncthreads();
    for (int off = 512; off > 0; off >>= 1) {
        if (tid < off) s[tid] += s[tid + off];
        __syncthreads();
    }
    if (tid == 0) out_loss[0] = (float)(s[0] / ((double)BSZ * (double)TSZ));
}

extern "C" void kernel_launch(void* const* d_in, const int* in_sizes, int n_in,
                              void* d_out, int out_size)
{
    const float* x    = (const float*)d_in[0];
    const int*   lens = (const int*)  d_in[1];
    const float* eWih = (const float*)d_in[2];
    const float* eWhh = (const float*)d_in[3];
    const float* ebih = (const float*)d_in[4];
    const float* ebhh = (const float*)d_in[5];
    const float* dWih = (const float*)d_in[6];
    const float* dWhh = (const float*)d_in[7];
    const float* dbih = (const float*)d_in[8];
    const float* dbhh = (const float*)d_in[9];
    const float* linW = (const float*)d_in[10];
    const float* linb = (const float*)d_in[11];

    float* out    = (float*)d_out;
    float* loss   = out;                       // [1]
    float* xpad   = out + 1;                   // [B*T]
    float* output = out + 1 + NTOT;            // [B*T]

    gru_kernel<<<BSZ / 32, 32>>>(x, lens, eWih, eWhh, ebih, ebhh,
                                 dWih, dWhh, dbih, dbhh, linW, linb,
                                 xpad, output);
    loss_kernel<<<1, 1024>>>(loss);
}

// round 11
// speedup vs baseline: 1.2238x; 1.2238x over previous
#include <cuda_runtime.h>

#define BSZ 4096
#define TSZ 4096
#define NTOT ((long)BSZ * TSZ)

#define FIN_BLOCKS 2048
#define FIN_THREADS 256

// raw (unmasked) decoder outputs, [B][T], 16B-aligned for vector stores
__device__ __align__(16) float g_o[NTOT];
// per-block loss partial sums from finalize kernel
__device__ double g_bsum[FIN_BLOCKS];

__device__ __forceinline__ float tanhx(float x) {
    float y; asm("tanh.approx.f32 %0, %1;" : "=f"(y) : "f"(x)); return y;
}

// One thread per batch element, all-scalar, chain-minimized.
// 128 blocks x 32 threads: 1 warp per SM (proven optimal spread).
__global__ void __launch_bounds__(32, 1) gru_kernel(
    const float* __restrict__ x, const int* __restrict__ lens,
    const float* __restrict__ eWih, const float* __restrict__ eWhh,
    const float* __restrict__ ebih, const float* __restrict__ ebhh,
    const float* __restrict__ dWih, const float* __restrict__ dWhh,
    const float* __restrict__ dbih, const float* __restrict__ dbhh,
    const float* __restrict__ linW, const float* __restrict__ linb)
{
    const int b   = blockIdx.x * 32 + threadIdx.x;
    const int len = lens[b];
    const float* __restrict__ xrow = x + (long)b * TSZ;

    float h0 = 0.f, h1 = 0.f, h2 = 0.f;
    float c0 = 0.f, c1 = 0.f, c2 = 0.f;      // captured h at t == len-1

    // ================= encoder =================
    {
        float wi[6], bs[6], w0[6], w1[6], w2[6];
#pragma unroll
        for (int g = 0; g < 6; g++) {
            wi[g] = 0.5f * eWih[g];
            bs[g] = 0.5f * (ebih[g] + ebhh[g]);
            w0[g] = 0.5f * eWhh[g * 3 + 0];
            w1[g] = 0.5f * eWhh[g * 3 + 1];
            w2[g] = 0.5f * eWhh[g * 3 + 2];
        }
        float win[3], bin_[3], bhn[3], wn0[3], wn1[3], wn2[3];
#pragma unroll
        for (int k = 0; k < 3; k++) {
            win[k]  = eWih[6 + k];
            bin_[k] = ebih[6 + k];
            bhn[k]  = ebhh[6 + k];
            wn0[k]  = eWhh[(6 + k) * 3 + 0];
            wn1[k]  = eWhh[(6 + k) * 3 + 1];
            wn2[k]  = eWhh[(6 + k) * 3 + 2];
        }
        const int len_m1 = len - 1;

        auto enc_step = [&](float xv, int t) {
            float gi[6];
#pragma unroll
            for (int g = 0; g < 6; g++) gi[g] = fmaf(xv, wi[g], bs[g]);
            float i0 = fmaf(xv, win[0], bin_[0]);
            float i1 = fmaf(xv, win[1], bin_[1]);
            float i2 = fmaf(xv, win[2], bin_[2]);

            float a[6];
#pragma unroll
            for (int g = 0; g < 6; g++)
                a[g] = fmaf(h2, w2[g], fmaf(h1, w1[g], fmaf(h0, w0[g], gi[g])));
            float hn0 = fmaf(h2, wn2[0], fmaf(h1, wn1[0], fmaf(h0, wn0[0], bhn[0])));
            float hn1 = fmaf(h2, wn2[1], fmaf(h1, wn1[1], fmaf(h0, wn0[1], bhn[1])));
            float hn2 = fmaf(h2, wn2[2], fmaf(h1, wn1[2], fmaf(h0, wn0[2], bhn[2])));

            // r-tanhs first: they feed the second MUFU wave
            float tr0 = tanhx(a[0]), tr1 = tanhx(a[1]), tr2 = tanhx(a[2]);
            float r0 = fmaf(tr0, 0.5f, 0.5f), r1 = fmaf(tr1, 0.5f, 0.5f), r2 = fmaf(tr2, 0.5f, 0.5f);
            float tz0 = tanhx(a[3]), tz1 = tanhx(a[4]), tz2 = tanhx(a[5]);
            float m0 = fmaf(tz0, -0.5f, 0.5f), m1 = fmaf(tz1, -0.5f, 0.5f), m2 = fmaf(tz2, -0.5f, 0.5f);

            float n0 = tanhx(fmaf(r0, hn0, i0));
            float n1 = tanhx(fmaf(r1, hn1, i1));
            float n2 = tanhx(fmaf(r2, hn2, i2));

            float nh0 = fmaf(m0, n0 - h0, h0);
            float nh1 = fmaf(m1, n1 - h1, h1);
            float nh2 = fmaf(m2, n2 - h2, h2);
            bool act = t < len;
            h0 = act ? nh0 : h0;
            h1 = act ? nh1 : h1;
            h2 = act ? nh2 : h2;
            if (t == len_m1) { c0 = h0; c1 = h1; c2 = h2; }
        };

        const int wmax  = __reduce_max_sync(0xFFFFFFFFu, len);
        const int wmax4 = (wmax + 3) & ~3;
        for (int t = 0; t < wmax4; t += 4) {
            const float4 xq = *(const float4*)(xrow + t);
            enc_step(xq.x, t + 0);
            enc_step(xq.y, t + 1);
            enc_step(xq.z, t + 2);
            enc_step(xq.w, t + 3);
        }
    }

    // features = sigmoid(captured h)
    h0 = fmaf(tanhx(0.5f * c0), 0.5f, 0.5f);
    h1 = fmaf(tanhx(0.5f * c1), 0.5f, 0.5f);
    h2 = fmaf(tanhx(0.5f * c2), 0.5f, 0.5f);

    // ================= decoder (linear layer folded into gates) =================
    {
        const float lw0 = linW[0], lw1 = linW[1], lw2 = linW[2], lb = linb[0];

        // rz gates: w'[g][k] = 0.5*(Whh[g][k] + Wih[g]*lw[k]); b' = 0.5*(bih+bhh+Wih[g]*lb)
        float w0f[6], w1f[6], w2f[6], bsf[6];
#pragma unroll
        for (int g = 0; g < 6; g++) {
            float wi = dWih[g];
            w0f[g] = 0.5f * fmaf(wi, lw0, dWhh[g * 3 + 0]);
            w1f[g] = 0.5f * fmaf(wi, lw1, dWhh[g * 3 + 1]);
            w2f[g] = 0.5f * fmaf(wi, lw2, dWhh[g * 3 + 2]);
            bsf[g] = 0.5f * (dbih[g] + dbhh[g] + wi * lb);
        }
        // n gates: i'[k] = (Wih_n[k]*lw)·h + (Wih_n[k]*lb + bih_n[k]);  hn unchanged
        float iw0[3], iw1[3], iw2[3], ibf[3], bhn[3], wn0[3], wn1[3], wn2[3];
#pragma unroll
        for (int k = 0; k < 3; k++) {
            float win = dWih[6 + k];
            iw0[k] = win * lw0;
            iw1[k] = win * lw1;
            iw2[k] = win * lw2;
            ibf[k] = fmaf(win, lb, dbih[6 + k]);
            bhn[k] = dbhh[6 + k];
            wn0[k] = dWhh[(6 + k) * 3 + 0];
            wn1[k] = dWhh[(6 + k) * 3 + 1];
            wn2[k] = dWhh[(6 + k) * 3 + 2];
        }

        float* __restrict__ grow = g_o + (long)b * TSZ;

        // folded step: pure function of h; outv is epilogue only
        auto dec_folded = [&]() -> float {
            float a[6];
#pragma unroll
            for (int g = 0; g < 6; g++)
                a[g] = fmaf(h2, w2f[g], fmaf(h1, w1f[g], fmaf(h0, w0f[g], bsf[g])));
            float hn0 = fmaf(h2, wn2[0], fmaf(h1, wn1[0], fmaf(h0, wn0[0], bhn[0])));
            float hn1 = fmaf(h2, wn2[1], fmaf(h1, wn1[1], fmaf(h0, wn0[1], bhn[1])));
            float hn2 = fmaf(h2, wn2[2], fmaf(h1, wn1[2], fmaf(h0, wn0[2], bhn[2])));
            float i0 = fmaf(h2, iw2[0], fmaf(h1, iw1[0], fmaf(h0, iw0[0], ibf[0])));
            float i1 = fmaf(h2, iw2[1], fmaf(h1, iw1[1], fmaf(h0, iw0[1], ibf[1])));
            float i2 = fmaf(h2, iw2[2], fmaf(h1, iw1[2], fmaf(h0, iw0[2], ibf[2])));

            float tr0 = tanhx(a[0]), tr1 = tanhx(a[1]), tr2 = tanhx(a[2]);
            float r0 = fmaf(tr0, 0.5f, 0.5f), r1 = fmaf(tr1, 0.5f, 0.5f), r2 = fmaf(tr2, 0.5f, 0.5f);
            float tz0 = tanhx(a[3]), tz1 = tanhx(a[4]), tz2 = tanhx(a[5]);
            float m0 = fmaf(tz0, -0.5f, 0.5f), m1 = fmaf(tz1, -0.5f, 0.5f), m2 = fmaf(tz2, -0.5f, 0.5f);

            float n0 = tanhx(fmaf(r0, hn0, i0));
            float n1 = tanhx(fmaf(r1, hn1, i1));
            float n2 = tanhx(fmaf(r2, hn2, i2));

            h0 = fmaf(m0, n0 - h0, h0);
            h1 = fmaf(m1, n1 - h1, h1);
            h2 = fmaf(m2, n2 - h2, h2);

            return fmaf(h2, lw2, fmaf(h1, lw1, fmaf(h0, lw0, lb)));
        };

        // ---- step 0 (inp = 0): unfolded ----
        float o_first;
        {
            float a[6];
#pragma unroll
            for (int g = 0; g < 6; g++)
                a[g] = 0.5f * (dbih[g] + dbhh[g]
                       + fmaf(h2, dWhh[g * 3 + 2], fmaf(h1, dWhh[g * 3 + 1], h0 * dWhh[g * 3 + 0])));
            float hn_[3], n_[3];
#pragma unroll
            for (int k = 0; k < 3; k++)
                hn_[k] = dbhh[6 + k]
                       + fmaf(h2, dWhh[(6 + k) * 3 + 2], fmaf(h1, dWhh[(6 + k) * 3 + 1], h0 * dWhh[(6 + k) * 3 + 0]));
#pragma unroll
            for (int k = 0; k < 3; k++) {
                float r = fmaf(tanhx(a[k]), 0.5f, 0.5f);
                n_[k] = tanhx(fmaf(r, hn_[k], dbih[6 + k]));
            }
            float m0 = fmaf(tanhx(a[3]), -0.5f, 0.5f);
            float m1 = fmaf(tanhx(a[4]), -0.5f, 0.5f);
            float m2 = fmaf(tanhx(a[5]), -0.5f, 0.5f);
            h0 = fmaf(m0, n_[0] - h0, h0);
            h1 = fmaf(m1, n_[1] - h1, h1);
            h2 = fmaf(m2, n_[2] - h2, h2);
            o_first = fmaf(h2, lw2, fmaf(h1, lw1, fmaf(h0, lw0, lb)));
        }
        // ---- steps 1..3, complete first store group ----
        {
            float o1 = dec_folded();
            float o2 = dec_folded();
            float o3 = dec_folded();
            *(float4*)(grow + 0) = make_float4(o_first, o1, o2, o3);
        }
        // ---- steps 4..4091, 8-wide unrolled store groups (511 iters) ----
        for (int t = 4; t < TSZ - 4; t += 8) {
            float o0 = dec_folded();
            float o1 = dec_folded();
            float o2 = dec_folded();
            float o3 = dec_folded();
            *(float4*)(grow + t) = make_float4(o0, o1, o2, o3);
            float o4 = dec_folded();
            float o5 = dec_folded();
            float o6 = dec_folded();
            float o7 = dec_folded();
            *(float4*)(grow + t + 4) = make_float4(o4, o5, o6, o7);
        }
        // ---- final steps 4092..4095 ----
        {
            float o0 = dec_folded();
            float o1 = dec_folded();
            float o2 = dec_folded();
            float o3 = dec_folded();
            *(float4*)(grow + TSZ - 4) = make_float4(o0, o1, o2, o3);
        }
    }
}

// Fused elementwise pass: xpad, masked output copy, loss partials.
__global__ void finalize_kernel(const float* __restrict__ x,
                                const int* __restrict__ lens,
                                float* __restrict__ xpad,
                                float* __restrict__ outmasked)
{
    __shared__ double s[FIN_THREADS];
    const int tid = threadIdx.x;
    float acc = 0.f;
    for (long idx = (long)blockIdx.x * FIN_THREADS + tid; idx < NTOT;
         idx += (long)FIN_BLOCKS * FIN_THREADS) {
        int b = (int)(idx >> 12);
        int t = (int)(idx & (TSZ - 1));
        bool v = t < lens[b];
        float xv = x[idx];
        float ov = g_o[idx];
        float xm = v ? xv : 0.f;
        float om = v ? ov : 0.f;
        xpad[idx]      = xm;
        outmasked[idx] = om;
        float d = xm - om;
        acc = fmaf(d, d, acc);
    }
    s[tid] = (double)acc;
    __syncthreads();
    for (int off = FIN_THREADS / 2; off > 0; off >>= 1) {
        if (tid < off) s[tid] += s[tid + off];
        __syncthreads();
    }
    if (tid == 0) g_bsum[blockIdx.x] = s[0];
}

// Deterministic fixed-order reduction of block partials -> scalar loss
__global__ void loss_kernel(float* __restrict__ out_loss)
{
    __shared__ double s[1024];
    int tid = threadIdx.x;
    double a = 0.0;
    for (int i = tid; i < FIN_BLOCKS; i += 1024) a += g_bsum[i];
    s[tid] = a;
    __syncthreads();
    for (int off = 512; off > 0; off >>= 1) {
        if (tid < off) s[tid] += s[tid + off];
        __syncthreads();
    }
    if (tid == 0) out_loss[0] = (float)(s[0] / ((double)BSZ * (double)TSZ));
}

extern "C" void kernel_launch(void* const* d_in, const int* in_sizes, int n_in,
                              void* d_out, int out_size)
{
    const float* x    = (const float*)d_in[0];
    const int*   lens = (const int*)  d_in[1];
    const float* eWih = (const float*)d_in[2];
    const float* eWhh = (const float*)d_in[3];
    const float* ebih = (const float*)d_in[4];
    const float* ebhh = (const float*)d_in[5];
    const float* dWih = (const float*)d_in[6];
    const float* dWhh = (const float*)d_in[7];
    const float* dbih = (const float*)d_in[8];
    const float* dbhh = (const float*)d_in[9];
    const float* linW = (const float*)d_in[10];
    const float* linb = (const float*)d_in[11];

    float* out    = (float*)d_out;
    float* loss   = out;                       // [1]
    float* xpad   = out + 1;                   // [B*T]
    float* output = out + 1 + NTOT;            // [B*T]

    gru_kernel<<<BSZ / 32, 32>>>(x, lens, eWih, eWhh, ebih, ebhh,
                                 dWih, dWhh, dbih, dbhh, linW, linb);
    finalize_kernel<<<FIN_BLOCKS, FIN_THREADS>>>(x, lens, xpad, output);
    loss_kernel<<<1, 1024>>>(loss);
}

// round 12
// speedup vs baseline: 1.6100x; 1.3156x over previous
#include <cuda_runtime.h>

#define BSZ 4096
#define TSZ 4096
#define NTOT ((long)BSZ * TSZ)

#define FIN_BLOCKS 2048
#define FIN_THREADS 256

// raw (unmasked) decoder outputs, [B][T], 16B-aligned for vector stores
__device__ __align__(16) float g_o[NTOT];
// per-block loss partial sums from finalize kernel
__device__ double g_bsum[FIN_BLOCKS];

__device__ __forceinline__ float tanhx(float x) {
    float y; asm("tanh.approx.f32 %0, %1;" : "=f"(y) : "f"(x)); return y;
}

// 4 lanes per chain (roles 0..2 own h0..h2, role 3 mirrors role 2 and stores).
// 8 chains per warp, 4 warps per block, 128 blocks -> 4096 chains, 1 warp/SMSP.
__global__ void __launch_bounds__(128, 1) gru_kernel(
    const float* __restrict__ x, const int* __restrict__ lens,
    const float* __restrict__ eWih, const float* __restrict__ eWhh,
    const float* __restrict__ ebih, const float* __restrict__ ebhh,
    const float* __restrict__ dWih, const float* __restrict__ dWhh,
    const float* __restrict__ dbih, const float* __restrict__ dbhh,
    const float* __restrict__ linW, const float* __restrict__ linb)
{
    const unsigned FULL = 0xFFFFFFFFu;
    const int lane  = threadIdx.x & 31;
    const int warp  = threadIdx.x >> 5;
    const int group = lane >> 2;
    const int role  = lane & 3;
    const int k     = (role == 3) ? 2 : role;
    int kA = k + 1; if (kA == 3) kA = 0;
    int kB = k + 2; if (kB >= 3) kB -= 3;
    const int base = lane & ~3;
    const int srcA = base + kA;
    const int srcB = base + kB;

    const int chain = (blockIdx.x * 4 + warp) * 8 + group;
    const int len   = lens[chain];
    const int len_m1 = len - 1;
    const float* __restrict__ xrow = x + (long)chain * TSZ;

    float h = 0.f, hA = 0.f, hB = 0.f;
    float c = 0.f;                         // captured own component at t == len-1

    // ================= encoder =================
    {
        // row k (r gate), row 3+k (z gate): pre-halved for sigmoid-via-tanh
        const float ewr_x = 0.5f * eWih[k];
        const float ewr_b = 0.5f * (ebih[k] + ebhh[k]);
        const float ewr_o = 0.5f * eWhh[k * 3 + k];
        const float ewr_A = 0.5f * eWhh[k * 3 + kA];
        const float ewr_B = 0.5f * eWhh[k * 3 + kB];
        const int zr = 3 + k;
        const float ewz_x = 0.5f * eWih[zr];
        const float ewz_b = 0.5f * (ebih[zr] + ebhh[zr]);
        const float ewz_o = 0.5f * eWhh[zr * 3 + k];
        const float ewz_A = 0.5f * eWhh[zr * 3 + kA];
        const float ewz_B = 0.5f * eWhh[zr * 3 + kB];
        const int nr = 6 + k;
        const float ewn_x  = eWih[nr];
        const float ewn_bi = ebih[nr];
        const float ewn_bh = ebhh[nr];
        const float ewn_o  = eWhh[nr * 3 + k];
        const float ewn_A  = eWhh[nr * 3 + kA];
        const float ewn_B  = eWhh[nr * 3 + kB];

        auto enc_step = [&](float xv, int t) {
            // x-parts: off-chain
            float gr = fmaf(xv, ewr_x, ewr_b);
            float gz = fmaf(xv, ewz_x, ewz_b);
            float gn = fmaf(xv, ewn_x, ewn_bi);
            // dots: own h innermost, shuffled values later
            float ar = fmaf(hB, ewr_B, fmaf(hA, ewr_A, fmaf(h, ewr_o, gr)));
            float az = fmaf(hB, ewz_B, fmaf(hA, ewz_A, fmaf(h, ewz_o, gz)));
            float hn = fmaf(hB, ewn_B, fmaf(hA, ewn_A, fmaf(h, ewn_o, ewn_bh)));
            float tr = tanhx(ar);
            float tz = tanhx(az);
            // na = r*hn + gn, r = 0.5*tr + 0.5  ->  na = tr*(0.5*hn) + (0.5*hn + gn)
            float p = 0.5f * hn;
            float q = fmaf(0.5f, hn, gn);
            float n = tanhx(fmaf(tr, p, q));
            // h' = (1-z)*n + z*h;  m = 1-z = -0.5*tz + 0.5;  u = z*h = h - m*h
            float m = fmaf(tz, -0.5f, 0.5f);
            float u = fmaf(-m, h, h);
            float nh = fmaf(n, m, u);
            bool act = t < len;
            h = act ? nh : h;
            if (t == len_m1) c = h;
            hA = __shfl_sync(FULL, h, srcA);
            hB = __shfl_sync(FULL, h, srcB);
        };

        const int wmax  = __reduce_max_sync(FULL, len);
        const int wmax4 = (wmax + 3) & ~3;
        for (int t = 0; t < wmax4; t += 4) {
            const float4 xq = *(const float4*)(xrow + t);
            enc_step(xq.x, t + 0);
            enc_step(xq.y, t + 1);
            enc_step(xq.z, t + 2);
            enc_step(xq.w, t + 3);
        }
    }

    // features = sigmoid(captured own component), then exchange
    h  = fmaf(tanhx(0.5f * c), 0.5f, 0.5f);
    hA = __shfl_sync(FULL, h, srcA);
    hB = __shfl_sync(FULL, h, srcB);

    // ================= decoder (linear layer folded into gates) =================
    {
        const float lw_o = linW[k], lw_A = linW[kA], lw_B = linW[kB], lb = linb[0];

        // r gate row k: w' = 0.5*(Whh + Wih*lw), b' = 0.5*(bih+bhh+Wih*lb)
        const float wik = dWih[k];
        const float dr_o = 0.5f * fmaf(wik, lw_o, dWhh[k * 3 + k]);
        const float dr_A = 0.5f * fmaf(wik, lw_A, dWhh[k * 3 + kA]);
        const float dr_B = 0.5f * fmaf(wik, lw_B, dWhh[k * 3 + kB]);
        const float dr_b = 0.5f * (dbih[k] + dbhh[k] + wik * lb);
        // z gate row 3+k
        const float wiz = dWih[3 + k];
        const float dz_o = 0.5f * fmaf(wiz, lw_o, dWhh[(3 + k) * 3 + k]);
        const float dz_A = 0.5f * fmaf(wiz, lw_A, dWhh[(3 + k) * 3 + kA]);
        const float dz_B = 0.5f * fmaf(wiz, lw_B, dWhh[(3 + k) * 3 + kB]);
        const float dz_b = 0.5f * (dbih[3 + k] + dbhh[3 + k] + wiz * lb);
        // n gate: i' = (Wih_n*lw)·h + (Wih_n*lb + bih_n); hn part unfolded
        const float win = dWih[6 + k];
        const float di_o = win * lw_o;
        const float di_A = win * lw_A;
        const float di_B = win * lw_B;
        const float di_b = fmaf(win, lb, dbih[6 + k]);
        const float dn_o = dWhh[(6 + k) * 3 + k];
        const float dn_A = dWhh[(6 + k) * 3 + kA];
        const float dn_B = dWhh[(6 + k) * 3 + kB];
        const float dn_b = dbhh[6 + k];

        float* __restrict__ grow = g_o + (long)chain * TSZ;

        auto dec_step = [&]() -> float {
            float ar = fmaf(hB, dr_B, fmaf(hA, dr_A, fmaf(h, dr_o, dr_b)));
            float az = fmaf(hB, dz_B, fmaf(hA, dz_A, fmaf(h, dz_o, dz_b)));
            float hn = fmaf(hB, dn_B, fmaf(hA, dn_A, fmaf(h, dn_o, dn_b)));
            float gi = fmaf(hB, di_B, fmaf(hA, di_A, fmaf(h, di_o, di_b)));
            float tr = tanhx(ar);
            float tz = tanhx(az);
            float p = 0.5f * hn;
            float q = fmaf(0.5f, hn, gi);
            float n = tanhx(fmaf(tr, p, q));
            float m = fmaf(tz, -0.5f, 0.5f);
            float u = fmaf(-m, h, h);
            h = fmaf(n, m, u);
            hA = __shfl_sync(FULL, h, srcA);
            hB = __shfl_sync(FULL, h, srcB);
            // full new h now present in every lane -> outv (epilogue)
            return fmaf(hB, lw_B, fmaf(hA, lw_A, fmaf(h, lw_o, lb)));
        };

        // ---- step 0 (inp = 0): unfolded, raw weights from global ----
        float o_first;
        {
            float ar = 0.5f * (dbih[k] + dbhh[k]
                     + fmaf(hB, dWhh[k * 3 + kB], fmaf(hA, dWhh[k * 3 + kA], h * dWhh[k * 3 + k])));
            float az = 0.5f * (dbih[3 + k] + dbhh[3 + k]
                     + fmaf(hB, dWhh[(3 + k) * 3 + kB], fmaf(hA, dWhh[(3 + k) * 3 + kA], h * dWhh[(3 + k) * 3 + k])));
            float hn = dbhh[6 + k]
                     + fmaf(hB, dWhh[(6 + k) * 3 + kB], fmaf(hA, dWhh[(6 + k) * 3 + kA], h * dWhh[(6 + k) * 3 + k]));
            float r = fmaf(tanhx(ar), 0.5f, 0.5f);
            float n = tanhx(fmaf(r, hn, dbih[6 + k]));
            float m = fmaf(tanhx(az), -0.5f, 0.5f);
            float u = fmaf(-m, h, h);
            h = fmaf(n, m, u);
            hA = __shfl_sync(FULL, h, srcA);
            hB = __shfl_sync(FULL, h, srcB);
            o_first = fmaf(hB, lw_B, fmaf(hA, lw_A, fmaf(h, lw_o, lb)));
        }
        // ---- steps 1..3, complete first store group ----
        {
            float o1 = dec_step();
            float o2 = dec_step();
            float o3 = dec_step();
            if (role == 3)
                *(float4*)(grow + 0) = make_float4(o_first, o1, o2, o3);
        }
        // ---- steps 4..4095: 1023 quads ----
        for (int t = 4; t < TSZ; t += 4) {
            float o0 = dec_step();
            float o1 = dec_step();
            float o2 = dec_step();
            float o3 = dec_step();
            if (role == 3)
                *(float4*)(grow + t) = make_float4(o0, o1, o2, o3);
        }
    }
}

// Fused elementwise pass: xpad, masked output copy, loss partials.
__global__ void finalize_kernel(const float* __restrict__ x,
                                const int* __restrict__ lens,
                                float* __restrict__ xpad,
                                float* __restrict__ outmasked)
{
    __shared__ double s[FIN_THREADS];
    const int tid = threadIdx.x;
    float acc = 0.f;
    for (long idx = (long)blockIdx.x * FIN_THREADS + tid; idx < NTOT;
         idx += (long)FIN_BLOCKS * FIN_THREADS) {
        int b = (int)(idx >> 12);
        int t = (int)(idx & (TSZ - 1));
        bool v = t < lens[b];
        float xv = x[idx];
        float ov = g_o[idx];
        float xm = v ? xv : 0.f;
        float om = v ? ov : 0.f;
        xpad[idx]      = xm;
        outmasked[idx] = om;
        float d = xm - om;
        acc = fmaf(d, d, acc);
    }
    s[tid] = (double)acc;
    __syncthreads();
    for (int off = FIN_THREADS / 2; off > 0; off >>= 1) {
        if (tid < off) s[tid] += s[tid + off];
        __syncthreads();
    }
    if (tid == 0) g_bsum[blockIdx.x] = s[0];
}

// Deterministic fixed-order reduction of block partials -> scalar loss
__global__ void loss_kernel(float* __restrict__ out_loss)
{
    __shared__ double s[1024];
    int tid = threadIdx.x;
    double a = 0.0;
    for (int i = tid; i < FIN_BLOCKS; i += 1024) a += g_bsum[i];
    s[tid] = a;
    __syncthreads();
    for (int off = 512; off > 0; off >>= 1) {
        if (tid < off) s[tid] += s[tid + off];
        __syncthreads();
    }
    if (tid == 0) out_loss[0] = (float)(s[0] / ((double)BSZ * (double)TSZ));
}

extern "C" void kernel_launch(void* const* d_in, const int* in_sizes, int n_in,
                              void* d_out, int out_size)
{
    const float* x    = (const float*)d_in[0];
    const int*   lens = (const int*)  d_in[1];
    const float* eWih = (const float*)d_in[2];
    const float* eWhh = (const float*)d_in[3];
    const float* ebih = (const float*)d_in[4];
    const float* ebhh = (const float*)d_in[5];
    const float* dWih = (const float*)d_in[6];
    const float* dWhh = (const float*)d_in[7];
    const float* dbih = (const float*)d_in[8];
    const float* dbhh = (const float*)d_in[9];
    const float* linW = (const float*)d_in[10];
    const float* linb = (const float*)d_in[11];

    float* out    = (float*)d_out;
    float* loss   = out;                       // [1]
    float* xpad   = out + 1;                   // [B*T]
    float* output = out + 1 + NTOT;            // [B*T]

    gru_kernel<<<128, 128>>>(x, lens, eWih, eWhh, ebih, ebhh,
                             dWih, dWhh, dbih, dbhh, linW, linb);
    finalize_kernel<<<FIN_BLOCKS, FIN_THREADS>>>(x, lens, xpad, output);
    loss_kernel<<<1, 1024>>>(loss);
}